// round 9
// baseline (speedup 1.0000x reference)
#include <cuda_runtime.h>
#include <cstdint>

#define Bb    8
#define Hh    512
#define Ll    8192
#define NFFT  16384
#define HALF  8192
#define QTOP  4096   /* NFFT/4 */
#define NPAIR 256    /* H/2 */
#define TFFT  1024
#define NTW   5461   /* 1+4+16+...+4096 */

// ---------------- scratch (device globals; no allocation allowed) ----------------
__device__ float4 g_AB[(size_t)NPAIR * (HALF + 1)];   // per-pair spectra, stored in pointwise iteration order
__device__ float  g_ymid[(size_t)Bb * Hh * Ll];       // conv+skip result (B,H,L), tf32-rounded
__device__ float  g_Wr[(size_t)Hh * Hh];              // W pre-rounded to tf32 (rna)
__device__ float2 g_tw1[NTW];                         // twiddle LUT: w, w^2, w^3 per (stage,j)
__device__ float2 g_tw2[NTW];
__device__ float2 g_tw3[NTW];

// ---------------- helpers ----------------
__device__ __forceinline__ float2 cmulf(float2 a, float2 b) {
    return make_float2(a.x * b.x - a.y * b.y, a.x * b.y + a.y * b.x);
}
__device__ __forceinline__ int rev4_14(int k) {
    unsigned r = __brev((unsigned)k) >> 18;
    return (int)(((r & 0x2AAAu) >> 1) | ((r & 0x1555u) << 1));
}
__device__ __forceinline__ float tf32r(float v) {
    uint32_t r;
    asm("cvt.rna.tf32.f32 %0, %1;" : "=r"(r) : "f"(v));
    return __uint_as_float(r);
}
// radix-4 DFT core (DIF pre-twiddle / DIT post-twiddle are the same arithmetic)
__device__ __forceinline__ void bf4(float2& a0, float2& a1, float2& a2, float2& a3) {
    float t0x = a0.x + a2.x, t0y = a0.y + a2.y;
    float t1x = a0.x - a2.x, t1y = a0.y - a2.y;
    float t2x = a1.x + a3.x, t2y = a1.y + a3.y;
    float t3x = a1.x - a3.x, t3y = a1.y - a3.y;
    a0 = make_float2(t0x + t2x, t0y + t2y);
    a1 = make_float2(t1x + t3y, t1y - t3x);   // t1 - i*t3
    a2 = make_float2(t0x - t2x, t0y - t2y);
    a3 = make_float2(t1x - t3y, t1y + t3x);   // t1 + i*t3
}

// ---------------- twiddle LUT init ----------------
__global__ void tw_init() {
    int idx = blockIdx.x * 256 + threadIdx.x;
    if (idx >= NTW) return;
    int q = 1, off = 0;
    while (idx >= off + q) { off += q; q <<= 2; }
    int j = idx - off;
    int m = q << 2;
    float ang = -6.283185307179586f * ((float)j / (float)m);
    float s1, c1, s2, c2, s3, c3;
    sincosf(ang, &s1, &c1);
    sincosf(2.0f * ang, &s2, &c2);
    sincosf(3.0f * ang, &s3, &c3);
    g_tw1[idx] = make_float2(c1, s1);
    g_tw2[idx] = make_float2(c2, s2);
    g_tw3[idx] = make_float2(c3, s3);
}

// ---------------- fused load + first DIF stage (m=NFFT, top half of input zero) ----------------
__device__ void dif_first_fused(float2* s, const float* __restrict__ f1,
                                const float* __restrict__ f2, int tid) {
#pragma unroll 2
    for (int i = tid; i < QTOP; i += TFFT) {
        float2 a0 = make_float2(f1[i], f2[i]);
        float2 a1 = make_float2(f1[i + QTOP], f2[i + QTOP]);
        float2 b0 = make_float2(a0.x + a1.x, a0.y + a1.y);
        float2 b1 = make_float2(a0.x + a1.y, a0.y - a1.x);   // a0 - i*a1
        float2 b2 = make_float2(a0.x - a1.x, a0.y - a1.y);
        float2 b3 = make_float2(a0.x - a1.y, a0.y + a1.x);   // a0 + i*a1
        float2 w1 = __ldg(&g_tw1[1365 + i]);
        float2 w2 = __ldg(&g_tw2[1365 + i]);
        float2 w3 = __ldg(&g_tw3[1365 + i]);
        s[i]            = b0;
        s[i + QTOP]     = cmulf(b1, w1);
        s[i + 2 * QTOP] = cmulf(b2, w2);
        s[i + 3 * QTOP] = cmulf(b3, w3);
    }
    __syncthreads();
}

// ---------------- mid DIF stages: m = 4096 .. 64 (conflict-free strides) ----------------
__device__ void dif_rest(float2* s, int tid) {
#pragma unroll 1
    for (int m = 4096; m >= 64; m >>= 2) {
        int q = m >> 2;
        int off = (q - 1) / 3;
#pragma unroll 2
        for (int i = tid; i < QTOP; i += TFFT) {
            int j = i & (q - 1);
            int base = ((i - j) << 2) + j;
            float2 a0 = s[base], a1 = s[base + q], a2 = s[base + 2 * q], a3 = s[base + 3 * q];
            bf4(a0, a1, a2, a3);
            float2 w1 = __ldg(&g_tw1[off + j]);
            float2 w2 = __ldg(&g_tw2[off + j]);
            float2 w3 = __ldg(&g_tw3[off + j]);
            s[base]         = a0;
            s[base + q]     = cmulf(a1, w1);
            s[base + 2 * q] = cmulf(a2, w2);
            s[base + 3 * q] = cmulf(a3, w3);
        }
        __syncthreads();
    }
}

// ---------------- merged DIF stages m=16 & m=4 in registers (rotated float4 access) ----------------
__device__ void dif_16_4(float2* s, int g) {
    float2 x[16];
    float4* s4 = (float4*)(s + 16 * g);
#pragma unroll
    for (int cc = 0; cc < 8; ++cc) {
        int c = (cc + g) & 7;
        float4 v = s4[c];
        x[2 * c]     = make_float2(v.x, v.y);
        x[2 * c + 1] = make_float2(v.z, v.w);
    }
    // stage m=16 (q=4), twiddle offset 1, j=0 twiddle = 1
#pragma unroll
    for (int j = 0; j < 4; ++j) {
        bf4(x[j], x[j + 4], x[j + 8], x[j + 12]);
        if (j) {
            float2 w1 = __ldg(&g_tw1[1 + j]);
            float2 w2 = __ldg(&g_tw2[1 + j]);
            float2 w3 = __ldg(&g_tw3[1 + j]);
            x[j + 4]  = cmulf(x[j + 4],  w1);
            x[j + 8]  = cmulf(x[j + 8],  w2);
            x[j + 12] = cmulf(x[j + 12], w3);
        }
    }
    // stage m=4 (q=1), twiddles = 1
#pragma unroll
    for (int a = 0; a < 4; ++a)
        bf4(x[4 * a], x[4 * a + 1], x[4 * a + 2], x[4 * a + 3]);
#pragma unroll
    for (int cc = 0; cc < 8; ++cc) {
        int c = (cc + g) & 7;
        s4[c] = make_float4(x[2 * c].x, x[2 * c].y, x[2 * c + 1].x, x[2 * c + 1].y);
    }
    __syncthreads();
}

// ---------------- merged DIT stages m=4 & m=16 in registers (rotated float4 access) ----------------
__device__ void dit_4_16(float2* s, int g) {
    float2 x[16];
    float4* s4 = (float4*)(s + 16 * g);
#pragma unroll
    for (int cc = 0; cc < 8; ++cc) {
        int c = (cc + g) & 7;
        float4 v = s4[c];
        x[2 * c]     = make_float2(v.x, v.y);
        x[2 * c + 1] = make_float2(v.z, v.w);
    }
    // stage m=4 (q=1): twiddles = 1
#pragma unroll
    for (int a = 0; a < 4; ++a)
        bf4(x[4 * a], x[4 * a + 1], x[4 * a + 2], x[4 * a + 3]);
    // stage m=16 (q=4): twiddle inputs then DFT4
#pragma unroll
    for (int j = 0; j < 4; ++j) {
        if (j) {
            float2 w1 = __ldg(&g_tw1[1 + j]);
            float2 w2 = __ldg(&g_tw2[1 + j]);
            float2 w3 = __ldg(&g_tw3[1 + j]);
            x[j + 4]  = cmulf(x[j + 4],  w1);
            x[j + 8]  = cmulf(x[j + 8],  w2);
            x[j + 12] = cmulf(x[j + 12], w3);
        }
        bf4(x[j], x[j + 4], x[j + 8], x[j + 12]);
    }
#pragma unroll
    for (int cc = 0; cc < 8; ++cc) {
        int c = (cc + g) & 7;
        s4[c] = make_float4(x[2 * c].x, x[2 * c].y, x[2 * c + 1].x, x[2 * c + 1].y);
    }
    __syncthreads();
}

// ---------------- mid DIT stages m = 64 .. 4096 ----------------
__device__ void dit_rest(float2* s, int tid) {
#pragma unroll 1
    for (int m = 64; m <= 4096; m <<= 2) {
        int q = m >> 2;
        int off = (q - 1) / 3;
#pragma unroll 2
        for (int i = tid; i < QTOP; i += TFFT) {
            int j = i & (q - 1);
            int base = ((i - j) << 2) + j;
            float2 c0 = s[base], c1 = s[base + q], c2 = s[base + 2 * q], c3 = s[base + 3 * q];
            float2 w1 = __ldg(&g_tw1[off + j]);
            float2 w2 = __ldg(&g_tw2[off + j]);
            float2 w3 = __ldg(&g_tw3[off + j]);
            c1 = cmulf(c1, w1);
            c2 = cmulf(c2, w2);
            c3 = cmulf(c3, w3);
            bf4(c0, c1, c2, c3);
            s[base]         = c0;
            s[base + q]     = c1;
            s[base + 2 * q] = c2;
            s[base + 3 * q] = c3;
        }
        __syncthreads();
    }
}

// ---------------- kernel 1: combined kernel spectra A,B per channel pair ----------------
// AB stored in pointwise iteration order: AB[i] <-> k = rev4(p(i)), p(i) = 4*(i>>1)+(i&1).
__global__ void __launch_bounds__(TFFT, 1) kf_kernel(const float* __restrict__ K) {
    extern __shared__ float2 s[];
    int tid  = threadIdx.x;
    int pair = blockIdx.x;
    const float* k1 = K + (size_t)(2 * pair) * Ll;
    const float* k2 = K + (size_t)(2 * pair + 1) * Ll;
    dif_first_fused(s, k1, k2, tid);
    dif_rest(s, tid);
    dif_16_4(s, tid);

    const float inv = 1.0f / (4.0f * (float)NFFT);
    float4* AB = g_AB + (size_t)pair * (HALF + 1);
#pragma unroll 2
    for (int i = tid; i < HALF; i += TFFT) {
        int p  = ((i >> 1) << 2) | (i & 1);
        int k  = rev4_14(p);
        int kn = (NFFT - k) & (NFFT - 1);
        int p2 = rev4_14(kn);
        float2 Z  = s[p];
        float2 Zp = s[p2];
        float ax = (Z.x + Z.y + Zp.x + Zp.y) * inv;
        float ay = (Z.y - Z.x + Zp.x - Zp.y) * inv;
        float bx = (Z.x - Z.y + Zp.x - Zp.y) * inv;
        float by = (Z.x + Z.y - Zp.x - Zp.y) * inv;
        AB[i] = make_float4(ax, ay, bx, by);
    }
    if (tid == 0) {  // k = 8192 (slot 2), self-paired: Zp = Z
        float2 Z = s[2];
        float ax = 2.f * (Z.x + Z.y) * inv;
        float bx = 2.f * (Z.x - Z.y) * inv;
        AB[HALF] = make_float4(ax, 0.f, bx, 0.f);
    }
}

// ---------------- kernel 2: FFT conv + skip per (batch, channel pair) ----------------
__global__ void __launch_bounds__(TFFT, 1) conv_kernel(const float* __restrict__ u,
                                                       const float* __restrict__ D) {
    extern __shared__ float2 s[];
    int tid  = threadIdx.x;
    int pair = blockIdx.x & (NPAIR - 1);
    int b    = blockIdx.x >> 8;
    int h1   = 2 * pair, h2 = h1 + 1;
    const float* u1 = u + ((size_t)b * Hh + h1) * Ll;
    const float* u2 = u + ((size_t)b * Hh + h2) * Ll;
    dif_first_fused(s, u1, u2, tid);
    dif_rest(s, tid);
    dif_16_4(s, tid);

    // pointwise in slot order: p = 4*(i>>1)+(i&1) covers exactly k in [0,8192)
    const float4* AB = g_AB + (size_t)pair * (HALF + 1);
#pragma unroll 2
    for (int i = tid; i < HALF; i += TFFT) {
        int p  = ((i >> 1) << 2) | (i & 1);
        int k  = rev4_14(p);
        int kn = (NFFT - k) & (NFFT - 1);
        int p2 = rev4_14(kn);
        float2 Z  = s[p];
        float2 Zp = s[p2];
        float4 ab = AB[i];
        float vx = Z.x * ab.x - Z.y * ab.y + Zp.x * ab.z + Zp.y * ab.w;
        float vy = Z.x * ab.y + Z.y * ab.x - Zp.y * ab.z + Zp.x * ab.w;
        s[p] = make_float2(vx, -vy);
        if (p != 0) {
            float wx =  Zp.x * ab.x + Zp.y * ab.y + Z.x * ab.z - Z.y * ab.w;
            float wy = -Zp.x * ab.y + Zp.y * ab.x - Z.x * ab.w - Z.y * ab.z;
            s[p2] = make_float2(wx, -wy);
        }
    }
    if (tid == 0) {  // k = 8192 (slot 2), self-paired
        float2 Z = s[2];
        float4 ab = AB[HALF];
        float vx = Z.x * ab.x - Z.y * ab.y + Z.x * ab.z + Z.y * ab.w;
        float vy = Z.x * ab.y + Z.y * ab.x - Z.y * ab.z + Z.x * ab.w;
        s[2] = make_float2(vx, -vy);
    }
    __syncthreads();

    dit_4_16(s, tid);
    dit_rest(s, tid);

    // fused last DIT stage (m=NFFT): only outputs n<8192 kept; write y directly.
    float d1 = D[h1], d2 = D[h2];
    float* y1 = g_ymid + ((size_t)b * Hh + h1) * Ll;
    float* y2 = g_ymid + ((size_t)b * Hh + h2) * Ll;
#pragma unroll 2
    for (int i = tid; i < QTOP; i += TFFT) {
        float2 c0 = s[i], c1 = s[i + QTOP], c2 = s[i + 2 * QTOP], c3 = s[i + 3 * QTOP];
        float2 w1 = __ldg(&g_tw1[1365 + i]);
        float2 w2 = __ldg(&g_tw2[1365 + i]);
        float2 w3 = __ldg(&g_tw3[1365 + i]);
        c1 = cmulf(c1, w1);
        c2 = cmulf(c2, w2);
        c3 = cmulf(c3, w3);
        float t0x = c0.x + c2.x, t0y = c0.y + c2.y;
        float t1x = c0.x - c2.x, t1y = c0.y - c2.y;
        float t2x = c1.x + c3.x, t2y = c1.y + c3.y;
        float t3x = c1.x - c3.x, t3y = c1.y - c3.y;
        float o0x = t0x + t2x, o0y = t0y + t2y;
        float o1x = t1x + t3y, o1y = t1y - t3x;
        y1[i]        = tf32r( o0x + d1 * u1[i]);
        y2[i]        = tf32r(-o0y + d2 * u2[i]);
        y1[i + QTOP] = tf32r( o1x + d1 * u1[i + QTOP]);
        y2[i + QTOP] = tf32r(-o1y + d2 * u2[i + QTOP]);
    }
}

// ---------------- kernel 2.5: pre-round W to tf32 (round-to-nearest) ----------------
__global__ void wround_kernel(const float* __restrict__ W) {
    int i = blockIdx.x * 256 + threadIdx.x;
    g_Wr[i] = tf32r(W[i]);
}

// ================= kernel 3: tf32 mma.sync mix GEMM + tanh =================
#define MIXT 256
#define AS_STR 36
#define BS_STR 136
#define A_BYTES (128 * AS_STR * 4)
#define B_BYTES (32 * BS_STR * 4)
#define STAGE_BYTES (A_BYTES + B_BYTES)
#define MIX_SMEM (2 * STAGE_BYTES)

__device__ __forceinline__ uint32_t smem_u32(const void* p) {
    uint32_t a;
    asm("{ .reg .u64 t; cvta.to.shared.u64 t, %1; cvt.u32.u64 %0, t; }" : "=r"(a) : "l"(p));
    return a;
}
__device__ __forceinline__ void mma_tf32(float* c, const uint32_t* a, const uint32_t* b) {
    asm volatile(
        "mma.sync.aligned.m16n8k8.row.col.f32.tf32.tf32.f32 "
        "{%0,%1,%2,%3}, {%4,%5,%6,%7}, {%8,%9}, {%0,%1,%2,%3};"
        : "+f"(c[0]), "+f"(c[1]), "+f"(c[2]), "+f"(c[3])
        : "r"(a[0]), "r"(a[1]), "r"(a[2]), "r"(a[3]), "r"(b[0]), "r"(b[1]));
}
__device__ __forceinline__ void load_stage(const float* __restrict__ Wp,
                                           const float* __restrict__ Yp,
                                           uint32_t smem_stage, int c, int tid) {
    int k0 = c * 32;
#pragma unroll
    for (int i = 0; i < 4; ++i) {
        int idx = tid + i * MIXT;
        int row = idx >> 3, seg = idx & 7;
        const float* src = Wp + (size_t)row * Hh + k0 + seg * 4;
        uint32_t dst = smem_stage + (uint32_t)(row * AS_STR + seg * 4) * 4;
        asm volatile("cp.async.cg.shared.global [%0], [%1], 16;" :: "r"(dst), "l"(src));
    }
#pragma unroll
    for (int i = 0; i < 4; ++i) {
        int idx = tid + i * MIXT;
        int row = idx >> 5, seg = idx & 31;
        const float* src = Yp + (size_t)(k0 + row) * Ll + seg * 4;
        uint32_t dst = smem_stage + A_BYTES + (uint32_t)(row * BS_STR + seg * 4) * 4;
        asm volatile("cp.async.cg.shared.global [%0], [%1], 16;" :: "r"(dst), "l"(src));
    }
    asm volatile("cp.async.commit_group;" ::: "memory");
}

__global__ void __launch_bounds__(MIXT, 2) mix_tc_kernel(float* __restrict__ out) {
    extern __shared__ char smx[];
    uint32_t sb = smem_u32(smx);
    int tid  = threadIdx.x;
    int lane = tid & 31, wid = tid >> 5;
    int warpM = wid >> 2, warpN = wid & 3;
    int g = lane >> 2, tg = lane & 3;

    int b     = blockIdx.z;
    int pTile = blockIdx.y * 128;
    int lTile = blockIdx.x * 128;
    const float* Wp = g_Wr + (size_t)pTile * Hh;
    const float* Yp = g_ymid + (size_t)b * Hh * Ll + lTile;
    float* Ob = out + (size_t)b * Hh * Ll;

    float acc[4][4][4];
#pragma unroll
    for (int mt = 0; mt < 4; ++mt)
#pragma unroll
        for (int nt = 0; nt < 4; ++nt)
#pragma unroll
            for (int r = 0; r < 4; ++r) acc[mt][nt][r] = 0.f;

    load_stage(Wp, Yp, sb, 0, tid);

#pragma unroll 1
    for (int c = 0; c < Hh / 32; ++c) {
        if (c + 1 < Hh / 32) {
            load_stage(Wp, Yp, sb + ((c + 1) & 1) * STAGE_BYTES, c + 1, tid);
            asm volatile("cp.async.wait_group 1;" ::: "memory");
        } else {
            asm volatile("cp.async.wait_group 0;" ::: "memory");
        }
        __syncthreads();

        const float* As = (const float*)(smx + (c & 1) * STAGE_BYTES);
        const float* Bs = (const float*)(smx + (c & 1) * STAGE_BYTES + A_BYTES);
#pragma unroll
        for (int ks = 0; ks < 4; ++ks) {
            uint32_t af[4][4], bf[4][2];
            int kc = ks * 8 + tg;
#pragma unroll
            for (int mt = 0; mt < 4; ++mt) {
                int r0 = warpM * 64 + mt * 16 + g;
                af[mt][0] = __float_as_uint(As[r0 * AS_STR + kc]);
                af[mt][1] = __float_as_uint(As[(r0 + 8) * AS_STR + kc]);
                af[mt][2] = __float_as_uint(As[r0 * AS_STR + kc + 4]);
                af[mt][3] = __float_as_uint(As[(r0 + 8) * AS_STR + kc + 4]);
            }
#pragma unroll
            for (int nt = 0; nt < 4; ++nt) {
                int l = warpN * 32 + nt * 8 + g;
                bf[nt][0] = __float_as_uint(Bs[kc * BS_STR + l]);
                bf[nt][1] = __float_as_uint(Bs[(kc + 4) * BS_STR + l]);
            }
#pragma unroll
            for (int mt = 0; mt < 4; ++mt)
#pragma unroll
                for (int nt = 0; nt < 4; ++nt)
                    mma_tf32(acc[mt][nt], af[mt], bf[nt]);
        }
        __syncthreads();
    }

#pragma unroll
    for (int mt = 0; mt < 4; ++mt) {
        int p0 = pTile + warpM * 64 + mt * 16 + g;
#pragma unroll
        for (int nt = 0; nt < 4; ++nt) {
            int l = lTile + warpN * 32 + nt * 8 + 2 * tg;
            float2 v0 = make_float2(tanhf(acc[mt][nt][0]), tanhf(acc[mt][nt][1]));
            float2 v1 = make_float2(tanhf(acc[mt][nt][2]), tanhf(acc[mt][nt][3]));
            *(float2*)(Ob + (size_t)p0 * Ll + l)       = v0;
            *(float2*)(Ob + (size_t)(p0 + 8) * Ll + l) = v1;
        }
    }
}

// ---------------- launch ----------------
extern "C" void kernel_launch(void* const* d_in, const int* in_sizes, int n_in,
                              void* d_out, int out_size) {
    const float* u = (const float*)d_in[0];
    const float* K = (const float*)d_in[1];
    const float* D = (const float*)d_in[2];
    const float* W = (const float*)d_in[3];
    float* out = (float*)d_out;

    const int smem = NFFT * (int)sizeof(float2);  // 128 KB
    cudaFuncSetAttribute(kf_kernel,   cudaFuncAttributeMaxDynamicSharedMemorySize, smem);
    cudaFuncSetAttribute(conv_kernel, cudaFuncAttributeMaxDynamicSharedMemorySize, smem);
    cudaFuncSetAttribute(mix_tc_kernel, cudaFuncAttributeMaxDynamicSharedMemorySize, MIX_SMEM);

    tw_init<<<(NTW + 255) / 256, 256>>>();
    wround_kernel<<<(Hh * Hh) / 256, 256>>>(W);
    kf_kernel<<<NPAIR, TFFT, smem>>>(K);
    conv_kernel<<<Bb * NPAIR, TFFT, smem>>>(u, D);
    dim3 g(Ll / 128, Hh / 128, Bb);
    mix_tc_kernel<<<g, MIXT, MIX_SMEM>>>(out);
}

// round 10
// speedup vs baseline: 2.8553x; 2.8553x over previous
#include <cuda_runtime.h>
#include <cstdint>

#define Bb    8
#define Hh    512
#define Ll    8192
#define NFFT  16384
#define HALF  8192
#define QTOP  4096   /* NFFT/4 */
#define NPAIR 256    /* H/2 */
#define TFFT  1024
#define NTW   5461   /* 1+4+16+...+4096 */

// ---------------- scratch (device globals; no allocation allowed) ----------------
__device__ float4 g_AB[(size_t)NPAIR * (HALF + 1)];   // per-pair spectra, pointwise iteration order
__device__ float  g_ymid[(size_t)Bb * Hh * Ll];       // conv+skip result (B,H,L), tf32-rounded
__device__ float  g_Wr[(size_t)Hh * Hh];              // W pre-rounded to tf32 (rna)
__device__ float2 g_tw1[NTW];                         // twiddle LUT per (stage,j)
__device__ float2 g_tw2[NTW];
__device__ float2 g_tw3[NTW];

// ---------------- helpers ----------------
__device__ __forceinline__ float2 cmulf(float2 a, float2 b) {
    return make_float2(a.x * b.x - a.y * b.y, a.x * b.y + a.y * b.x);
}
__device__ __forceinline__ int rev4_14(int k) {
    unsigned r = __brev((unsigned)k) >> 18;
    return (int)(((r & 0x2AAAu) >> 1) | ((r & 0x1555u) << 1));
}
__device__ __forceinline__ float tf32r(float v) {
    uint32_t r;
    asm("cvt.rna.tf32.f32 %0, %1;" : "=r"(r) : "f"(v));
    return __uint_as_float(r);
}
// bank swizzle: XOR bits[4:6) into bit-pairs [0:2) and [2:4)  -> q=4 / q=1 stages conflict-free
__device__ __forceinline__ int sw(int n) {
    return n ^ (((n >> 4) & 3) * 5);
}
// radix-4 DFT core
__device__ __forceinline__ void bf4(float2& a0, float2& a1, float2& a2, float2& a3) {
    float t0x = a0.x + a2.x, t0y = a0.y + a2.y;
    float t1x = a0.x - a2.x, t1y = a0.y - a2.y;
    float t2x = a1.x + a3.x, t2y = a1.y + a3.y;
    float t3x = a1.x - a3.x, t3y = a1.y - a3.y;
    a0 = make_float2(t0x + t2x, t0y + t2y);
    a1 = make_float2(t1x + t3y, t1y - t3x);   // t1 - i*t3
    a2 = make_float2(t0x - t2x, t0y - t2y);
    a3 = make_float2(t1x - t3y, t1y + t3x);   // t1 + i*t3
}

// ---------------- twiddle LUT init ----------------
__global__ void tw_init() {
    int idx = blockIdx.x * 256 + threadIdx.x;
    if (idx >= NTW) return;
    int q = 1, off = 0;
    while (idx >= off + q) { off += q; q <<= 2; }
    int j = idx - off;
    int m = q << 2;
    float ang = -6.283185307179586f * ((float)j / (float)m);
    float s1, c1, s2, c2, s3, c3;
    sincosf(ang, &s1, &c1);
    sincosf(2.0f * ang, &s2, &c2);
    sincosf(3.0f * ang, &s3, &c3);
    g_tw1[idx] = make_float2(c1, s1);
    g_tw2[idx] = make_float2(c2, s2);
    g_tw3[idx] = make_float2(c3, s3);
}

// ---------------- fused load + first DIF stage (m=NFFT, top half zero) ----------------
__device__ void dif_first_fused(float2* s, const float* __restrict__ f1,
                                const float* __restrict__ f2, int tid) {
#pragma unroll 2
    for (int i = tid; i < QTOP; i += TFFT) {
        float2 a0 = make_float2(f1[i], f2[i]);
        float2 a1 = make_float2(f1[i + QTOP], f2[i + QTOP]);
        float2 b0 = make_float2(a0.x + a1.x, a0.y + a1.y);
        float2 b1 = make_float2(a0.x + a1.y, a0.y - a1.x);   // a0 - i*a1
        float2 b2 = make_float2(a0.x - a1.x, a0.y - a1.y);
        float2 b3 = make_float2(a0.x - a1.y, a0.y + a1.x);   // a0 + i*a1
        float2 w1 = __ldg(&g_tw1[1365 + i]);
        float2 w2 = __ldg(&g_tw2[1365 + i]);
        float2 w3 = __ldg(&g_tw3[1365 + i]);
        s[sw(i)]            = b0;
        s[sw(i + QTOP)]     = cmulf(b1, w1);
        s[sw(i + 2 * QTOP)] = cmulf(b2, w2);
        s[sw(i + 3 * QTOP)] = cmulf(b3, w3);
    }
    __syncthreads();
}

// ---------------- DIF stages m = 4096 .. 4 ----------------
__device__ void dif_rest(float2* s, int tid) {
#pragma unroll 1
    for (int m = 4096; m >= 4; m >>= 2) {
        int q = m >> 2;
        int off = (q - 1) / 3;
#pragma unroll 2
        for (int i = tid; i < QTOP; i += TFFT) {
            int j = i & (q - 1);
            int base = ((i - j) << 2) + j;
            int i0 = sw(base), i1 = sw(base + q), i2 = sw(base + 2 * q), i3 = sw(base + 3 * q);
            float2 a0 = s[i0], a1 = s[i1], a2 = s[i2], a3 = s[i3];
            bf4(a0, a1, a2, a3);
            float2 w1 = __ldg(&g_tw1[off + j]);
            float2 w2 = __ldg(&g_tw2[off + j]);
            float2 w3 = __ldg(&g_tw3[off + j]);
            s[i0] = a0;
            s[i1] = cmulf(a1, w1);
            s[i2] = cmulf(a2, w2);
            s[i3] = cmulf(a3, w3);
        }
        __syncthreads();
    }
}

// ---------------- DIT stages m = 4 .. 4096 (last stage fused by caller) ----------------
__device__ void dit_rest(float2* s, int tid) {
#pragma unroll 1
    for (int m = 4; m <= 4096; m <<= 2) {
        int q = m >> 2;
        int off = (q - 1) / 3;
#pragma unroll 2
        for (int i = tid; i < QTOP; i += TFFT) {
            int j = i & (q - 1);
            int base = ((i - j) << 2) + j;
            int i0 = sw(base), i1 = sw(base + q), i2 = sw(base + 2 * q), i3 = sw(base + 3 * q);
            float2 c0 = s[i0], c1 = s[i1], c2 = s[i2], c3 = s[i3];
            float2 w1 = __ldg(&g_tw1[off + j]);
            float2 w2 = __ldg(&g_tw2[off + j]);
            float2 w3 = __ldg(&g_tw3[off + j]);
            c1 = cmulf(c1, w1);
            c2 = cmulf(c2, w2);
            c3 = cmulf(c3, w3);
            bf4(c0, c1, c2, c3);
            s[i0] = c0;
            s[i1] = c1;
            s[i2] = c2;
            s[i3] = c3;
        }
        __syncthreads();
    }
}

// ---------------- kernel 1: combined kernel spectra A,B per channel pair ----------------
// AB stored in pointwise iteration order: AB[i] <-> k = rev4(p(i)), p(i) = 4*(i>>1)+(i&1).
__global__ void __launch_bounds__(TFFT, 1) kf_kernel(const float* __restrict__ K) {
    extern __shared__ float2 s[];
    int tid  = threadIdx.x;
    int pair = blockIdx.x;
    const float* k1 = K + (size_t)(2 * pair) * Ll;
    const float* k2 = K + (size_t)(2 * pair + 1) * Ll;
    dif_first_fused(s, k1, k2, tid);
    dif_rest(s, tid);

    const float inv = 1.0f / (4.0f * (float)NFFT);
    float4* AB = g_AB + (size_t)pair * (HALF + 1);
#pragma unroll 2
    for (int i = tid; i < HALF; i += TFFT) {
        int p  = ((i >> 1) << 2) | (i & 1);
        int k  = rev4_14(p);
        int kn = (NFFT - k) & (NFFT - 1);
        int p2 = rev4_14(kn);
        float2 Z  = s[sw(p)];
        float2 Zp = s[sw(p2)];
        float ax = (Z.x + Z.y + Zp.x + Zp.y) * inv;
        float ay = (Z.y - Z.x + Zp.x - Zp.y) * inv;
        float bx = (Z.x - Z.y + Zp.x - Zp.y) * inv;
        float by = (Z.x + Z.y - Zp.x - Zp.y) * inv;
        AB[i] = make_float4(ax, ay, bx, by);
    }
    if (tid == 0) {  // k = 8192 (slot 2), self-paired: Zp = Z
        float2 Z = s[sw(2)];
        float ax = 2.f * (Z.x + Z.y) * inv;
        float bx = 2.f * (Z.x - Z.y) * inv;
        AB[HALF] = make_float4(ax, 0.f, bx, 0.f);
    }
}

// ---------------- kernel 2: FFT conv + skip per (batch, channel pair) ----------------
__global__ void __launch_bounds__(TFFT, 1) conv_kernel(const float* __restrict__ u,
                                                       const float* __restrict__ D) {
    extern __shared__ float2 s[];
    int tid  = threadIdx.x;
    int pair = blockIdx.x & (NPAIR - 1);
    int b    = blockIdx.x >> 8;
    int h1   = 2 * pair, h2 = h1 + 1;
    const float* u1 = u + ((size_t)b * Hh + h1) * Ll;
    const float* u2 = u + ((size_t)b * Hh + h2) * Ll;
    dif_first_fused(s, u1, u2, tid);
    dif_rest(s, tid);

    // pointwise in slot order: p = 4*(i>>1)+(i&1) covers exactly k in [0,8192)
    const float4* AB = g_AB + (size_t)pair * (HALF + 1);
#pragma unroll 2
    for (int i = tid; i < HALF; i += TFFT) {
        int p  = ((i >> 1) << 2) | (i & 1);
        int k  = rev4_14(p);
        int kn = (NFFT - k) & (NFFT - 1);
        int p2 = rev4_14(kn);
        int sp = sw(p), sp2 = sw(p2);
        float2 Z  = s[sp];
        float2 Zp = s[sp2];
        float4 ab = AB[i];
        float vx = Z.x * ab.x - Z.y * ab.y + Zp.x * ab.z + Zp.y * ab.w;
        float vy = Z.x * ab.y + Z.y * ab.x - Zp.y * ab.z + Zp.x * ab.w;
        s[sp] = make_float2(vx, -vy);
        if (p != 0) {
            float wx =  Zp.x * ab.x + Zp.y * ab.y + Z.x * ab.z - Z.y * ab.w;
            float wy = -Zp.x * ab.y + Zp.y * ab.x - Z.x * ab.w - Z.y * ab.z;
            s[sp2] = make_float2(wx, -wy);
        }
    }
    if (tid == 0) {  // k = 8192 (slot 2), self-paired
        float2 Z = s[sw(2)];
        float4 ab = AB[HALF];
        float vx = Z.x * ab.x - Z.y * ab.y + Z.x * ab.z + Z.y * ab.w;
        float vy = Z.x * ab.y + Z.y * ab.x - Z.y * ab.z + Z.x * ab.w;
        s[sw(2)] = make_float2(vx, -vy);
    }
    __syncthreads();

    dit_rest(s, tid);

    // fused last DIT stage (m=NFFT): only outputs n<8192 kept; write y directly.
    float d1 = D[h1], d2 = D[h2];
    float* y1 = g_ymid + ((size_t)b * Hh + h1) * Ll;
    float* y2 = g_ymid + ((size_t)b * Hh + h2) * Ll;
#pragma unroll 2
    for (int i = tid; i < QTOP; i += TFFT) {
        float2 c0 = s[sw(i)], c1 = s[sw(i + QTOP)], c2 = s[sw(i + 2 * QTOP)], c3 = s[sw(i + 3 * QTOP)];
        float2 w1 = __ldg(&g_tw1[1365 + i]);
        float2 w2 = __ldg(&g_tw2[1365 + i]);
        float2 w3 = __ldg(&g_tw3[1365 + i]);
        c1 = cmulf(c1, w1);
        c2 = cmulf(c2, w2);
        c3 = cmulf(c3, w3);
        float t0x = c0.x + c2.x, t0y = c0.y + c2.y;
        float t1x = c0.x - c2.x, t1y = c0.y - c2.y;
        float t2x = c1.x + c3.x, t2y = c1.y + c3.y;
        float t3x = c1.x - c3.x, t3y = c1.y - c3.y;
        float o0x = t0x + t2x, o0y = t0y + t2y;
        float o1x = t1x + t3y, o1y = t1y - t3x;
        y1[i]        = tf32r( o0x + d1 * u1[i]);
        y2[i]        = tf32r(-o0y + d2 * u2[i]);
        y1[i + QTOP] = tf32r( o1x + d1 * u1[i + QTOP]);
        y2[i + QTOP] = tf32r(-o1y + d2 * u2[i + QTOP]);
    }
}

// ---------------- kernel 2.5: pre-round W to tf32 (round-to-nearest) ----------------
__global__ void wround_kernel(const float* __restrict__ W) {
    int i = blockIdx.x * 256 + threadIdx.x;
    g_Wr[i] = tf32r(W[i]);
}

// ================= kernel 3: tf32 mma.sync mix GEMM + tanh =================
#define MIXT 256
#define AS_STR 36
#define BS_STR 136
#define A_BYTES (128 * AS_STR * 4)
#define B_BYTES (32 * BS_STR * 4)
#define STAGE_BYTES (A_BYTES + B_BYTES)
#define MIX_SMEM (2 * STAGE_BYTES)

__device__ __forceinline__ uint32_t smem_u32(const void* p) {
    uint32_t a;
    asm("{ .reg .u64 t; cvta.to.shared.u64 t, %1; cvt.u32.u64 %0, t; }" : "=r"(a) : "l"(p));
    return a;
}
__device__ __forceinline__ void mma_tf32(float* c, const uint32_t* a, const uint32_t* b) {
    asm volatile(
        "mma.sync.aligned.m16n8k8.row.col.f32.tf32.tf32.f32 "
        "{%0,%1,%2,%3}, {%4,%5,%6,%7}, {%8,%9}, {%0,%1,%2,%3};"
        : "+f"(c[0]), "+f"(c[1]), "+f"(c[2]), "+f"(c[3])
        : "r"(a[0]), "r"(a[1]), "r"(a[2]), "r"(a[3]), "r"(b[0]), "r"(b[1]));
}
__device__ __forceinline__ void load_stage(const float* __restrict__ Wp,
                                           const float* __restrict__ Yp,
                                           uint32_t smem_stage, int c, int tid) {
    int k0 = c * 32;
#pragma unroll
    for (int i = 0; i < 4; ++i) {
        int idx = tid + i * MIXT;
        int row = idx >> 3, seg = idx & 7;
        const float* src = Wp + (size_t)row * Hh + k0 + seg * 4;
        uint32_t dst = smem_stage + (uint32_t)(row * AS_STR + seg * 4) * 4;
        asm volatile("cp.async.cg.shared.global [%0], [%1], 16;" :: "r"(dst), "l"(src));
    }
#pragma unroll
    for (int i = 0; i < 4; ++i) {
        int idx = tid + i * MIXT;
        int row = idx >> 5, seg = idx & 31;
        const float* src = Yp + (size_t)(k0 + row) * Ll + seg * 4;
        uint32_t dst = smem_stage + A_BYTES + (uint32_t)(row * BS_STR + seg * 4) * 4;
        asm volatile("cp.async.cg.shared.global [%0], [%1], 16;" :: "r"(dst), "l"(src));
    }
    asm volatile("cp.async.commit_group;" ::: "memory");
}

__global__ void __launch_bounds__(MIXT, 2) mix_tc_kernel(float* __restrict__ out) {
    extern __shared__ char smx[];
    uint32_t sb = smem_u32(smx);
    int tid  = threadIdx.x;
    int lane = tid & 31, wid = tid >> 5;
    int warpM = wid >> 2, warpN = wid & 3;
    int g = lane >> 2, tg = lane & 3;

    int b     = blockIdx.z;
    int pTile = blockIdx.y * 128;
    int lTile = blockIdx.x * 128;
    const float* Wp = g_Wr + (size_t)pTile * Hh;
    const float* Yp = g_ymid + (size_t)b * Hh * Ll + lTile;
    float* Ob = out + (size_t)b * Hh * Ll;

    float acc[4][4][4];
#pragma unroll
    for (int mt = 0; mt < 4; ++mt)
#pragma unroll
        for (int nt = 0; nt < 4; ++nt)
#pragma unroll
            for (int r = 0; r < 4; ++r) acc[mt][nt][r] = 0.f;

    load_stage(Wp, Yp, sb, 0, tid);

#pragma unroll 1
    for (int c = 0; c < Hh / 32; ++c) {
        if (c + 1 < Hh / 32) {
            load_stage(Wp, Yp, sb + ((c + 1) & 1) * STAGE_BYTES, c + 1, tid);
            asm volatile("cp.async.wait_group 1;" ::: "memory");
        } else {
            asm volatile("cp.async.wait_group 0;" ::: "memory");
        }
        __syncthreads();

        const float* As = (const float*)(smx + (c & 1) * STAGE_BYTES);
        const float* Bs = (const float*)(smx + (c & 1) * STAGE_BYTES + A_BYTES);
#pragma unroll
        for (int ks = 0; ks < 4; ++ks) {
            uint32_t af[4][4], bf[4][2];
            int kc = ks * 8 + tg;
#pragma unroll
            for (int mt = 0; mt < 4; ++mt) {
                int r0 = warpM * 64 + mt * 16 + g;
                af[mt][0] = __float_as_uint(As[r0 * AS_STR + kc]);
                af[mt][1] = __float_as_uint(As[(r0 + 8) * AS_STR + kc]);
                af[mt][2] = __float_as_uint(As[r0 * AS_STR + kc + 4]);
                af[mt][3] = __float_as_uint(As[(r0 + 8) * AS_STR + kc + 4]);
            }
#pragma unroll
            for (int nt = 0; nt < 4; ++nt) {
                int l = warpN * 32 + nt * 8 + g;
                bf[nt][0] = __float_as_uint(Bs[kc * BS_STR + l]);
                bf[nt][1] = __float_as_uint(Bs[(kc + 4) * BS_STR + l]);
            }
#pragma unroll
            for (int mt = 0; mt < 4; ++mt)
#pragma unroll
                for (int nt = 0; nt < 4; ++nt)
                    mma_tf32(acc[mt][nt], af[mt], bf[nt]);
        }
        __syncthreads();
    }

#pragma unroll
    for (int mt = 0; mt < 4; ++mt) {
        int p0 = pTile + warpM * 64 + mt * 16 + g;
#pragma unroll
        for (int nt = 0; nt < 4; ++nt) {
            int l = lTile + warpN * 32 + nt * 8 + 2 * tg;
            float2 v0 = make_float2(tanhf(acc[mt][nt][0]), tanhf(acc[mt][nt][1]));
            float2 v1 = make_float2(tanhf(acc[mt][nt][2]), tanhf(acc[mt][nt][3]));
            *(float2*)(Ob + (size_t)p0 * Ll + l)       = v0;
            *(float2*)(Ob + (size_t)(p0 + 8) * Ll + l) = v1;
        }
    }
}

// ---------------- launch ----------------
extern "C" void kernel_launch(void* const* d_in, const int* in_sizes, int n_in,
                              void* d_out, int out_size) {
    const float* u = (const float*)d_in[0];
    const float* K = (const float*)d_in[1];
    const float* D = (const float*)d_in[2];
    const float* W = (const float*)d_in[3];
    float* out = (float*)d_out;

    const int smem = NFFT * (int)sizeof(float2);  // 128 KB
    cudaFuncSetAttribute(kf_kernel,   cudaFuncAttributeMaxDynamicSharedMemorySize, smem);
    cudaFuncSetAttribute(conv_kernel, cudaFuncAttributeMaxDynamicSharedMemorySize, smem);
    cudaFuncSetAttribute(mix_tc_kernel, cudaFuncAttributeMaxDynamicSharedMemorySize, MIX_SMEM);

    tw_init<<<(NTW + 255) / 256, 256>>>();
    wround_kernel<<<(Hh * Hh) / 256, 256>>>(W);
    kf_kernel<<<NPAIR, TFFT, smem>>>(K);
    conv_kernel<<<Bb * NPAIR, TFFT, smem>>>(u, D);
    dim3 g(Ll / 128, Hh / 128, Bb);
    mix_tc_kernel<<<g, MIXT, MIX_SMEM>>>(out);
}